// round 8
// baseline (speedup 1.0000x reference)
#include <cuda_runtime.h>
#include <cstdint>

#define BB 512
#define SS 4096
#define DD 128
#define KK 409
#define VV 6
#define CS 4            // chunks per row
#define CHUNK 1024      // tokens per chunk
#define NT 256
#define TBLK (2 * VV)   // 12 table CTAs, scheduled first

// -------- global scratch (plain overwrites / self-resetting counter) --------
__device__ int   g_hist[BB][CS][VV];
__device__ int   g_sel [BB][CS][VV];
__device__ float g_sc  [VV];
__device__ float g_att [VV * DD];
__device__ int   g_arrive[BB];          // 0 at load; reset to 0 by finisher

// ===========================================================================
// K1: blocks 0..5   -> score MLP for class bid        (scheduled FIRST)
//     blocks 6..11  -> attention MLP for class bid-6
//     blocks 12..   -> per-chunk histograms (2048 CTAs, 1 int4/thread)
// ===========================================================================
__global__ void __launch_bounds__(NT)
k1_hist_tables(const int* __restrict__ x,
               const float* __restrict__ emb,
               const float* __restrict__ W1, const float* __restrict__ b1,
               const float* __restrict__ W2, const float* __restrict__ b2,
               const float* __restrict__ W3, const float* __restrict__ b3,
               const float* __restrict__ A1, const float* __restrict__ a1,
               const float* __restrict__ A2, const float* __restrict__ a2) {
    const int tid = threadIdx.x;

    if (blockIdx.x >= TBLK) {
        // ---------------- histogram CTA (one 1024-token chunk) ----------------
        const int gbid = blockIdx.x - TBLK;
        const int row = gbid >> 2, ch = gbid & 3;
        const int w = tid >> 5, lane = tid & 31;

        const int4 t = *reinterpret_cast<const int4*>(
            x + (size_t)row * SS + (size_t)ch * CHUNK + (size_t)tid * 4);

        // packed 10-bit-per-class counter (per-warp max 128/class: fits)
        unsigned long long c = 0;
        c += 1ULL << (10 * t.x); c += 1ULL << (10 * t.y);
        c += 1ULL << (10 * t.z); c += 1ULL << (10 * t.w);
        #pragma unroll
        for (int o = 16; o; o >>= 1) c += __shfl_down_sync(0xFFFFFFFFu, c, o);

        __shared__ unsigned long long wred[8];
        if (lane == 0) wred[w] = c;
        __syncthreads();

        if (tid < VV) {
            int s = 0;
            #pragma unroll
            for (int i = 0; i < 8; i++) s += (int)((wred[i] >> (10 * tid)) & 1023ULL);
            g_hist[row][ch][tid] = s;
        }
        return;
    }

    // ---------------- table CTAs (start in wave 1) ----------------
    const int bid = blockIdx.x;
    __shared__ float e_s[DD];
    __shared__ float h1_s[64];
    __shared__ float h2_s[32];

    const int v = (bid < VV) ? bid : bid - VV;
    if (tid < DD) e_s[tid] = emb[v * DD + tid];
    __syncthreads();

    if (bid < VV) {
        // ======== score chain: e -> h1(64) -> h2(32) -> score ========
        {   // h1: 4 threads per neuron, 8 independent accumulators
            const int n = tid >> 2, q = tid & 3;
            const int i0 = q * 32;
            float acc[8] = {0, 0, 0, 0, 0, 0, 0, 0};
            #pragma unroll
            for (int m = 0; m < 4; m++)
                #pragma unroll
                for (int j = 0; j < 8; j++) {
                    const int i = i0 + m * 8 + j;
                    acc[j] = fmaf(e_s[i], W1[i * 64 + n], acc[j]);
                }
            float s = ((acc[0] + acc[1]) + (acc[2] + acc[3]))
                    + ((acc[4] + acc[5]) + (acc[6] + acc[7]));
            s += __shfl_down_sync(0xFFFFFFFFu, s, 2);
            s += __shfl_down_sync(0xFFFFFFFFu, s, 1);
            if (q == 0) h1_s[n] = fmaxf(s + b1[n], 0.f);
        }
        __syncthreads();
        {   // h2: 8 threads per neuron
            const int n = tid >> 3, r = tid & 7;
            float acc[8];
            #pragma unroll
            for (int j = 0; j < 8; j++) {
                const int i = r + 8 * j;
                acc[j] = h1_s[i] * W2[i * 32 + n];
            }
            float s = ((acc[0] + acc[1]) + (acc[2] + acc[3]))
                    + ((acc[4] + acc[5]) + (acc[6] + acc[7]));
            s += __shfl_down_sync(0xFFFFFFFFu, s, 4);
            s += __shfl_down_sync(0xFFFFFFFFu, s, 2);
            s += __shfl_down_sync(0xFFFFFFFFu, s, 1);
            if (r == 0) h2_s[n] = fmaxf(s + b2[n], 0.f);
        }
        __syncthreads();
        if (tid < 32) {
            float s = h2_s[tid] * W3[tid];
            #pragma unroll
            for (int o = 16; o; o >>= 1) s += __shfl_down_sync(0xFFFFFFFFu, s, o);
            if (tid == 0) g_sc[v] = 1.f / (1.f + expf(-(s + b3[0])));
        }
    } else {
        // ======== attention chain: e -> g(64) -> att(128) ========
        {   // g: 4 threads per neuron
            const int n = tid >> 2, q = tid & 3;
            const int i0 = q * 32;
            float acc[8] = {0, 0, 0, 0, 0, 0, 0, 0};
            #pragma unroll
            for (int m = 0; m < 4; m++)
                #pragma unroll
                for (int j = 0; j < 8; j++) {
                    const int i = i0 + m * 8 + j;
                    acc[j] = fmaf(e_s[i], A1[i * 64 + n], acc[j]);
                }
            float s = ((acc[0] + acc[1]) + (acc[2] + acc[3]))
                    + ((acc[4] + acc[5]) + (acc[6] + acc[7]));
            s += __shfl_down_sync(0xFFFFFFFFu, s, 2);
            s += __shfl_down_sync(0xFFFFFFFFu, s, 1);
            if (q == 0) h1_s[n] = fmaxf(s + a1[n], 0.f);   // g
        }
        __syncthreads();
        {   // att: 2 threads per output dim
            const int d = tid >> 1, q = tid & 1;
            const int j0 = q * 32;
            float acc[8] = {0, 0, 0, 0, 0, 0, 0, 0};
            #pragma unroll
            for (int m = 0; m < 4; m++)
                #pragma unroll
                for (int jj = 0; jj < 8; jj++) {
                    const int j = j0 + m * 8 + jj;
                    acc[jj] = fmaf(h1_s[j], A2[j * DD + d], acc[jj]);
                }
            float s = ((acc[0] + acc[1]) + (acc[2] + acc[3]))
                    + ((acc[4] + acc[5]) + (acc[6] + acc[7]));
            s += __shfl_down_sync(0xFFFFFFFFu, s, 1);
            if (q == 0) g_att[v * DD + d] = s + a2[d];
        }
    }
}

// ===========================================================================
// K2: 2048 chunk-CTAs. fs LUT writes, ranked top-k scatter, sel counts.
//     Last-arriving CTA per row additionally pools + classifies (fused K3).
// ===========================================================================
__global__ void __launch_bounds__(NT)
k2_rank(const int* __restrict__ x,
        const float* __restrict__ C1, const float* __restrict__ c1,
        const float* __restrict__ C2, const float* __restrict__ c2,
        float* __restrict__ out) {
    const int row = blockIdx.x >> 2, ch = blockIdx.x & 3;
    const int tid = threadIdx.x;

    __shared__ float sc_s[VV];
    __shared__ int   hsm[CS][VV];
    __shared__ int   pref[VV][NT];
    __shared__ int   base_s[VV];
    __shared__ unsigned eqm_s[VV];
    __shared__ int   wls[8][VV];
    __shared__ int   is_last;
    __shared__ int   selcnt[VV];
    __shared__ float pooled[DD];
    __shared__ float hbuf[64];

    float* __restrict__ top_out = out + BB;
    float* __restrict__ fs_out  = out + BB + (size_t)BB * KK;

    // early loads (hidden behind everything before first barrier)
    if (tid < VV) sc_s[tid] = g_sc[tid];
    if (tid >= 192 && tid < 192 + CS * VV)
        hsm[(tid - 192) / VV][(tid - 192) % VV] = g_hist[row][(tid - 192) / VV][(tid - 192) % VV];

    const int4 tv = *reinterpret_cast<const int4*>(
        x + (size_t)row * SS + (size_t)ch * CHUNK + (size_t)tid * 4);
    const int tok[4] = {tv.x, tv.y, tv.z, tv.w};

    #pragma unroll
    for (int u = 0; u < VV; u++) {
        int c = 0;
        #pragma unroll
        for (int l = 0; l < 4; l++) c += (tok[l] == u);
        pref[u][tid] = c;
    }
    __syncthreads();

    // fs writes (all warps) — sc_s now visible
    {
        float4 f;
        f.x = sc_s[tok[0]]; f.y = sc_s[tok[1]]; f.z = sc_s[tok[2]]; f.w = sc_s[tok[3]];
        *reinterpret_cast<float4*>(fs_out + (size_t)row * SS + (size_t)ch * CHUNK
                                   + (size_t)tid * 4) = f;
    }

    // warps 0-5: scan class w; warp 6: base/eqm from smem hist
    {
        const int w = tid >> 5, lane = tid & 31;
        if (w < VV) {
            int vals[8]; int sum = 0;
            #pragma unroll
            for (int i = 0; i < 8; i++) { vals[i] = pref[w][lane * 8 + i]; sum += vals[i]; }
            int incl = sum;
            #pragma unroll
            for (int off = 1; off < 32; off <<= 1) {
                int n = __shfl_up_sync(0xFFFFFFFFu, incl, off);
                if (lane >= off) incl += n;
            }
            int excl = incl - sum;
            #pragma unroll
            for (int i = 0; i < 8; i++) { const int t = vals[i]; pref[w][lane * 8 + i] = excl; excl += t; }
        } else if (w == 6 && lane < VV) {
            const float sv = sc_s[lane];
            int b = 0; unsigned m = 0;
            #pragma unroll
            for (int u = 0; u < VV; u++) {
                const float su = sc_s[u];
                const int tu = hsm[0][u] + hsm[1][u] + hsm[2][u] + hsm[3][u];
                if (su > sv) b += tu;
                if (su == sv) {
                    m |= 1u << u;
                    for (int r = 0; r < ch; r++) b += hsm[r][u];
                }
            }
            base_s[lane] = b; eqm_s[lane] = m;
        }
    }
    __syncthreads();

    // ranked scatter + selected counts
    int ls[VV] = {0, 0, 0, 0, 0, 0};
    {
        int P[VV];
        #pragma unroll
        for (int u = 0; u < VV; u++) P[u] = pref[u][tid];
        int rc[VV] = {0, 0, 0, 0, 0, 0};
        const size_t obase = (size_t)row * KK;
        const int gp0 = ch * CHUNK + tid * 4;
        #pragma unroll
        for (int l = 0; l < 4; l++) {
            const int v = tok[l];
            const unsigned m = eqm_s[v];
            int r = base_s[v];
            #pragma unroll
            for (int u = 0; u < VV; u++)
                if ((m >> u) & 1u) r += P[u] + rc[u];
            #pragma unroll
            for (int u = 0; u < VV; u++) rc[u] += (v == u);
            if (r < KK) {
                top_out[obase + r] = (float)(gp0 + l);
                #pragma unroll
                for (int u = 0; u < VV; u++) ls[u] += (v == u);
            }
        }
    }
    #pragma unroll
    for (int u = 0; u < VV; u++) {
        #pragma unroll
        for (int o = 16; o; o >>= 1) ls[u] += __shfl_down_sync(0xFFFFFFFFu, ls[u], o);
    }
    {
        const int w = tid >> 5, lane = tid & 31;
        if (lane == 0) {
            #pragma unroll
            for (int u = 0; u < VV; u++) wls[w][u] = ls[u];
        }
    }
    __syncthreads();
    if (tid < VV) {
        int s = 0;
        #pragma unroll
        for (int i = 0; i < 8; i++) s += wls[i][tid];
        g_sel[row][ch][tid] = s;
    }
    __syncthreads();

    // ---- arrival protocol: 4th CTA of the row runs pooling + classifier ----
    if (tid == 0) {
        __threadfence();
        is_last = (atomicAdd(&g_arrive[row], 1) == CS - 1);
    }
    __syncthreads();
    if (!is_last) return;

    __threadfence();                       // acquire peers' g_sel stores
    if (tid == 0) g_arrive[row] = 0;       // self-reset for next graph replay

    if (tid < VV) {
        int s = 0;
        #pragma unroll
        for (int r = 0; r < CS; r++) s += g_sel[row][r][tid];
        selcnt[tid] = s;
    }
    __syncthreads();

    if (tid < DD) {
        float s = 0.f;
        #pragma unroll
        for (int v = 0; v < VV; v++)
            s = fmaf((float)selcnt[v], g_att[v * DD + tid], s);
        pooled[tid] = s / (float)KK;
    }
    __syncthreads();

    {   // classifier layer 1: 64 neurons x 4 threads, 8-way ILP
        const int n = tid >> 2, q = tid & 3;
        const int i0 = q * 32;
        float acc[8] = {0, 0, 0, 0, 0, 0, 0, 0};
        #pragma unroll
        for (int m = 0; m < 4; m++)
            #pragma unroll
            for (int j = 0; j < 8; j++) {
                const int i = i0 + m * 8 + j;
                acc[j] = fmaf(pooled[i], C1[i * 64 + n], acc[j]);
            }
        float s = ((acc[0] + acc[1]) + (acc[2] + acc[3]))
                + ((acc[4] + acc[5]) + (acc[6] + acc[7]));
        s += __shfl_down_sync(0xFFFFFFFFu, s, 2);
        s += __shfl_down_sync(0xFFFFFFFFu, s, 1);
        if (q == 0) hbuf[n] = fmaxf(s + c1[n], 0.f);
    }
    __syncthreads();

    if (tid < 32) {
        float s = fmaf(hbuf[tid], C2[tid], hbuf[tid + 32] * C2[tid + 32]);
        #pragma unroll
        for (int o = 16; o; o >>= 1) s += __shfl_down_sync(0xFFFFFFFFu, s, o);
        if (tid == 0) out[row] = 1.f / (1.f + expf(-(s + c2[0])));
    }
}

// ===========================================================================
extern "C" void kernel_launch(void* const* d_in, const int* in_sizes, int n_in,
                              void* d_out, int out_size) {
    const int*   x   = (const int*)  d_in[0];
    const float* emb = (const float*)d_in[1];
    const float* W1  = (const float*)d_in[2];
    const float* b1  = (const float*)d_in[3];
    const float* W2  = (const float*)d_in[4];
    const float* b2  = (const float*)d_in[5];
    const float* W3  = (const float*)d_in[6];
    const float* b3  = (const float*)d_in[7];
    const float* A1  = (const float*)d_in[8];
    const float* a1  = (const float*)d_in[9];
    const float* A2  = (const float*)d_in[10];
    const float* a2  = (const float*)d_in[11];
    const float* C1  = (const float*)d_in[12];
    const float* c1  = (const float*)d_in[13];
    const float* C2  = (const float*)d_in[14];
    const float* c2  = (const float*)d_in[15];
    float* out = (float*)d_out;

    k1_hist_tables<<<TBLK + BB * CS, NT>>>(x, emb, W1, b1, W2, b2, W3, b3,
                                           A1, a1, A2, a2);
    k2_rank<<<BB * CS, NT>>>(x, C1, c1, C2, c2, out);
}

// round 10
// speedup vs baseline: 1.4672x; 1.4672x over previous
#include <cuda_runtime.h>
#include <cstdint>

#define BB 512
#define SS 4096
#define DD 128
#define KK 409
#define VV 6
#define CS 4            // chunks per row
#define CHUNK 1024      // tokens per chunk
#define NT 256
#define TBLK (2 * VV)   // 12 table CTAs, scheduled first

// -------- global scratch (plain overwrites only; deterministic) --------
__device__ int   g_hist[BB][CS][VV];
__device__ int   g_sel [BB][CS][VV];   // written only on the (unreachable) tie path
__device__ float g_sc  [VV];
__device__ float g_U   [VV][64];       // U[v][n] = att_v . C1[:,n]

// ===========================================================================
// K1: blocks 0..5   -> score MLP for class bid        (scheduled FIRST)
//     blocks 6..11  -> attention MLP + U precompute for class bid-6
//     blocks 12..   -> per-chunk histograms (2048 CTAs, 1 int4/thread)
// ===========================================================================
__global__ void __launch_bounds__(NT)
k1_hist_tables(const int* __restrict__ x,
               const float* __restrict__ emb,
               const float* __restrict__ W1, const float* __restrict__ b1,
               const float* __restrict__ W2, const float* __restrict__ b2,
               const float* __restrict__ W3, const float* __restrict__ b3,
               const float* __restrict__ A1, const float* __restrict__ a1,
               const float* __restrict__ A2, const float* __restrict__ a2,
               const float* __restrict__ C1) {
    const int tid = threadIdx.x;

    if (blockIdx.x >= TBLK) {
        // ---------------- histogram CTA (one 1024-token chunk) ----------------
        const int gbid = blockIdx.x - TBLK;
        const int row = gbid >> 2, ch = gbid & 3;
        const int w = tid >> 5, lane = tid & 31;

        const int4 t = *reinterpret_cast<const int4*>(
            x + (size_t)row * SS + (size_t)ch * CHUNK + (size_t)tid * 4);

        unsigned long long c = 0;
        c += 1ULL << (10 * t.x); c += 1ULL << (10 * t.y);
        c += 1ULL << (10 * t.z); c += 1ULL << (10 * t.w);
        #pragma unroll
        for (int o = 16; o; o >>= 1) c += __shfl_down_sync(0xFFFFFFFFu, c, o);

        __shared__ unsigned long long wred[8];
        if (lane == 0) wred[w] = c;
        __syncthreads();

        if (tid < VV) {
            int s = 0;
            #pragma unroll
            for (int i = 0; i < 8; i++) s += (int)((wred[i] >> (10 * tid)) & 1023ULL);
            g_hist[row][ch][tid] = s;
        }
        return;
    }

    // ---------------- table CTAs (start in wave 1) ----------------
    const int bid = blockIdx.x;
    __shared__ float e_s[DD];
    __shared__ float h1_s[64];
    __shared__ float h2_s[32];
    __shared__ float att_s[DD];

    const int v = (bid < VV) ? bid : bid - VV;
    if (tid < DD) e_s[tid] = emb[v * DD + tid];
    __syncthreads();

    if (bid < VV) {
        // ======== score chain: e -> h1(64) -> h2(32) -> score ========
        {   // h1: 4 threads per neuron, 8 independent accumulators
            const int n = tid >> 2, q = tid & 3;
            const int i0 = q * 32;
            float acc[8] = {0, 0, 0, 0, 0, 0, 0, 0};
            #pragma unroll
            for (int m = 0; m < 4; m++)
                #pragma unroll
                for (int j = 0; j < 8; j++) {
                    const int i = i0 + m * 8 + j;
                    acc[j] = fmaf(e_s[i], W1[i * 64 + n], acc[j]);
                }
            float s = ((acc[0] + acc[1]) + (acc[2] + acc[3]))
                    + ((acc[4] + acc[5]) + (acc[6] + acc[7]));
            s += __shfl_down_sync(0xFFFFFFFFu, s, 2);
            s += __shfl_down_sync(0xFFFFFFFFu, s, 1);
            if (q == 0) h1_s[n] = fmaxf(s + b1[n], 0.f);
        }
        __syncthreads();
        {   // h2: 8 threads per neuron
            const int n = tid >> 3, r = tid & 7;
            float acc[8];
            #pragma unroll
            for (int j = 0; j < 8; j++) {
                const int i = r + 8 * j;
                acc[j] = h1_s[i] * W2[i * 32 + n];
            }
            float s = ((acc[0] + acc[1]) + (acc[2] + acc[3]))
                    + ((acc[4] + acc[5]) + (acc[6] + acc[7]));
            s += __shfl_down_sync(0xFFFFFFFFu, s, 4);
            s += __shfl_down_sync(0xFFFFFFFFu, s, 2);
            s += __shfl_down_sync(0xFFFFFFFFu, s, 1);
            if (r == 0) h2_s[n] = fmaxf(s + b2[n], 0.f);
        }
        __syncthreads();
        if (tid < 32) {
            float s = h2_s[tid] * W3[tid];
            #pragma unroll
            for (int o = 16; o; o >>= 1) s += __shfl_down_sync(0xFFFFFFFFu, s, o);
            if (tid == 0) g_sc[v] = 1.f / (1.f + expf(-(s + b3[0])));
        }
    } else {
        // ======== attention chain: e -> g(64) -> att(128) -> U(64) ========
        {   // g: 4 threads per neuron
            const int n = tid >> 2, q = tid & 3;
            const int i0 = q * 32;
            float acc[8] = {0, 0, 0, 0, 0, 0, 0, 0};
            #pragma unroll
            for (int m = 0; m < 4; m++)
                #pragma unroll
                for (int j = 0; j < 8; j++) {
                    const int i = i0 + m * 8 + j;
                    acc[j] = fmaf(e_s[i], A1[i * 64 + n], acc[j]);
                }
            float s = ((acc[0] + acc[1]) + (acc[2] + acc[3]))
                    + ((acc[4] + acc[5]) + (acc[6] + acc[7]));
            s += __shfl_down_sync(0xFFFFFFFFu, s, 2);
            s += __shfl_down_sync(0xFFFFFFFFu, s, 1);
            if (q == 0) h1_s[n] = fmaxf(s + a1[n], 0.f);   // g
        }
        __syncthreads();
        {   // att: 2 threads per output dim
            const int d = tid >> 1, q = tid & 1;
            const int j0 = q * 32;
            float acc[8] = {0, 0, 0, 0, 0, 0, 0, 0};
            #pragma unroll
            for (int m = 0; m < 4; m++)
                #pragma unroll
                for (int jj = 0; jj < 8; jj++) {
                    const int j = j0 + m * 8 + jj;
                    acc[jj] = fmaf(h1_s[j], A2[j * DD + d], acc[jj]);
                }
            float s = ((acc[0] + acc[1]) + (acc[2] + acc[3]))
                    + ((acc[4] + acc[5]) + (acc[6] + acc[7]));
            s += __shfl_down_sync(0xFFFFFFFFu, s, 1);
            if (q == 0) att_s[d] = s + a2[d];
        }
        __syncthreads();
        {   // U[v][n] = att . C1[:,n]  (4 threads per neuron, 8-way ILP)
            const int n = tid >> 2, q = tid & 3;
            const int i0 = q * 32;
            float acc[8] = {0, 0, 0, 0, 0, 0, 0, 0};
            #pragma unroll
            for (int m = 0; m < 4; m++)
                #pragma unroll
                for (int j = 0; j < 8; j++) {
                    const int i = i0 + m * 8 + j;
                    acc[j] = fmaf(att_s[i], C1[i * 64 + n], acc[j]);
                }
            float s = ((acc[0] + acc[1]) + (acc[2] + acc[3]))
                    + ((acc[4] + acc[5]) + (acc[6] + acc[7]));
            s += __shfl_down_sync(0xFFFFFFFFu, s, 2);
            s += __shfl_down_sync(0xFFFFFFFFu, s, 1);
            if (q == 0) g_U[v][n] = s;
        }
    }
}

// ===========================================================================
// K2: 2048 chunk-CTAs. fs LUT writes + ranked top-k scatter.
//     Packed-u64 prefix scan; register-only inner loop; tie-exact slow path.
// ===========================================================================
__global__ void __launch_bounds__(NT)
k2_rank(const int* __restrict__ x, float* __restrict__ out) {
    const int row = blockIdx.x >> 2, ch = blockIdx.x & 3;
    const int tid = threadIdx.x;
    const int w = tid >> 5, lane = tid & 31;

    __shared__ float sc_s[8];
    __shared__ int   hsm[CS][VV];
    __shared__ unsigned long long wtot[8];
    __shared__ int   wls[8][VV];       // tie path only

    float* __restrict__ top_out = out + BB;
    float* __restrict__ fs_out  = out + BB + (size_t)BB * KK;

    // early global loads (latency hidden before the single barrier)
    if (tid < VV) sc_s[tid] = g_sc[tid];
    if (tid >= 32 && tid < 32 + CS * VV)
        hsm[(tid - 32) / VV][(tid - 32) % VV] = g_hist[row][(tid - 32) / VV][(tid - 32) % VV];

    const int4 tv = *reinterpret_cast<const int4*>(
        x + (size_t)row * SS + (size_t)ch * CHUNK + (size_t)tid * 4);
    const int tok[4] = {tv.x, tv.y, tv.z, tv.w};

    // packed per-thread counts + warp-inclusive scan (u64, 10 bits/class)
    unsigned long long c = 0;
    c += 1ULL << (10 * tok[0]); c += 1ULL << (10 * tok[1]);
    c += 1ULL << (10 * tok[2]); c += 1ULL << (10 * tok[3]);
    unsigned long long incl = c;
    #pragma unroll
    for (int off = 1; off < 32; off <<= 1) {
        unsigned long long n = __shfl_up_sync(0xFFFFFFFFu, incl, off);
        if (lane >= off) incl += n;
    }
    if (lane == 31) wtot[w] = incl;
    __syncthreads();

    // exclusive packed prefix across the whole chunk
    unsigned long long E = incl - c;
    for (int i = 0; i < w; i++) E += wtot[i];

    // per-warp: lanes 0..5 compute base (strict-greater totals + equal-score
    // earlier-chunk prefix) and the equality mask; derive uniform tie flag
    int b = 0; unsigned m = 0;
    if (lane < VV) {
        const float sv = sc_s[lane];
        #pragma unroll
        for (int u = 0; u < VV; u++) {
            const float su = sc_s[u];
            const int tu = hsm[0][u] + hsm[1][u] + hsm[2][u] + hsm[3][u];
            if (su > sv) b += tu;
            if (su == sv) {
                m |= 1u << u;
                for (int r = 0; r < ch; r++) b += hsm[r][u];
            }
        }
    }
    const bool tie =
        __ballot_sync(0xFFFFFFFFu, (lane < VV) && (m != (1u << lane))) != 0;

    // final_scores (LUT, float4)
    {
        float4 f;
        f.x = sc_s[tok[0]]; f.y = sc_s[tok[1]]; f.z = sc_s[tok[2]]; f.w = sc_s[tok[3]];
        *reinterpret_cast<float4*>(fs_out + (size_t)row * SS + (size_t)ch * CHUNK
                                   + (size_t)tid * 4) = f;
    }

    const size_t obase = (size_t)row * KK;
    const int gp0 = ch * CHUNK + tid * 4;

    if (!tie) {
        // -------- fast path: single-class rank, register-only --------
        #pragma unroll
        for (int l = 0; l < 4; l++) {
            const int v = tok[l];
            const int base = __shfl_sync(0xFFFFFFFFu, b, v);
            const int r = base + (int)((E >> (10 * v)) & 1023ULL);
            E += 1ULL << (10 * v);
            if (r < KK) top_out[obase + r] = (float)(gp0 + l);
        }
        return;   // selcnt computed analytically in K3
    }

    // -------- tie path (exact lax.top_k semantics; unreachable in practice) --
    int ls[VV] = {0, 0, 0, 0, 0, 0};
    #pragma unroll
    for (int l = 0; l < 4; l++) {
        const int v = tok[l];
        const unsigned mv = __shfl_sync(0xFFFFFFFFu, m, v);
        int r = __shfl_sync(0xFFFFFFFFu, b, v);
        #pragma unroll
        for (int u = 0; u < VV; u++)
            if ((mv >> u) & 1u) r += (int)((E >> (10 * u)) & 1023ULL);
        E += 1ULL << (10 * v);
        if (r < KK) {
            top_out[obase + r] = (float)(gp0 + l);
            #pragma unroll
            for (int u = 0; u < VV; u++) ls[u] += (v == u);
        }
    }
    #pragma unroll
    for (int u = 0; u < VV; u++) {
        #pragma unroll
        for (int o = 16; o; o >>= 1) ls[u] += __shfl_down_sync(0xFFFFFFFFu, ls[u], o);
    }
    if (lane == 0) {
        #pragma unroll
        for (int u = 0; u < VV; u++) wls[w][u] = ls[u];
    }
    __syncthreads();
    if (tid < VV) {
        int s = 0;
        #pragma unroll
        for (int i = 0; i < 8; i++) s += wls[i][tid];
        g_sel[row][ch][tid] = s;
    }
}

// ===========================================================================
// K3: per-row classifier via precomputed U. 512 blocks x 64 threads.
//     selcnt analytic from g_hist (no ties); g_sel fallback for ties.
// ===========================================================================
__global__ void __launch_bounds__(64)
k3_classify(const float* __restrict__ c1,
            const float* __restrict__ C2, const float* __restrict__ c2,
            float* __restrict__ out) {
    const int row = blockIdx.x;
    const int tid = threadIdx.x;

    __shared__ float sc_s[8];
    __shared__ int   hs[CS][VV];
    __shared__ float scf[VV];
    __shared__ int   tie_s;
    __shared__ float part[2];

    if (tid < CS * VV) hs[tid / VV][tid % VV] = g_hist[row][tid / VV][tid % VV];
    if (tid >= 32 && tid < 32 + VV) sc_s[tid - 32] = g_sc[tid - 32];
    if (tid == 63) tie_s = 0;
    __syncthreads();

    if (tid < VV) {
        const float sv = sc_s[tid];
        int b = 0, tot = 0; unsigned m = 0;
        #pragma unroll
        for (int u = 0; u < VV; u++) {
            const float su = sc_s[u];
            const int tu = hs[0][u] + hs[1][u] + hs[2][u] + hs[3][u];
            if (su > sv) b += tu;
            if (su == sv) m |= 1u << u;
            if (u == tid) tot = tu;
        }
        if (m != (1u << tid)) atomicOr(&tie_s, 1);
        int sel = KK - b;
        sel = sel < 0 ? 0 : (sel > tot ? tot : sel);
        scf[tid] = (float)sel;
    }
    __syncthreads();

    if (tie_s && tid < VV) {   // unreachable fallback: exact counts from K2
        int s = 0;
        #pragma unroll
        for (int r = 0; r < CS; r++) s += g_sel[row][r][tid];
        scf[tid] = (float)s;
    }
    if (tie_s) __syncthreads();

    // h_n = relu( sum_v (cnt_v/K) * U[v][n] + c1_n ); pred = sigmoid(h.C2+c2)
    const float inv = 1.0f / (float)KK;
    float acc = c1[tid];
    #pragma unroll
    for (int v = 0; v < VV; v++)
        acc = fmaf(scf[v] * inv, g_U[v][tid], acc);
    float h = fmaxf(acc, 0.f) * C2[tid];
    #pragma unroll
    for (int o = 16; o; o >>= 1) h += __shfl_down_sync(0xFFFFFFFFu, h, o);
    if ((tid & 31) == 0) part[tid >> 5] = h;
    __syncthreads();
    if (tid == 0)
        out[row] = 1.f / (1.f + expf(-(part[0] + part[1] + c2[0])));
}

// ===========================================================================
extern "C" void kernel_launch(void* const* d_in, const int* in_sizes, int n_in,
                              void* d_out, int out_size) {
    const int*   x   = (const int*)  d_in[0];
    const float* emb = (const float*)d_in[1];
    const float* W1  = (const float*)d_in[2];
    const float* b1  = (const float*)d_in[3];
    const float* W2  = (const float*)d_in[4];
    const float* b2  = (const float*)d_in[5];
    const float* W3  = (const float*)d_in[6];
    const float* b3  = (const float*)d_in[7];
    const float* A1  = (const float*)d_in[8];
    const float* a1  = (const float*)d_in[9];
    const float* A2  = (const float*)d_in[10];
    const float* a2  = (const float*)d_in[11];
    const float* C1  = (const float*)d_in[12];
    const float* c1  = (const float*)d_in[13];
    const float* C2  = (const float*)d_in[14];
    const float* c2  = (const float*)d_in[15];
    float* out = (float*)d_out;

    k1_hist_tables<<<TBLK + BB * CS, NT>>>(x, emb, W1, b1, W2, b2, W3, b3,
                                           A1, a1, A2, a2, C1);
    k2_rank<<<BB * CS, NT>>>(x, out);
    k3_classify<<<BB, 64>>>(c1, C2, c2, out);
}

// round 11
// speedup vs baseline: 2.0360x; 1.3877x over previous
#include <cuda_runtime.h>
#include <cstdint>

#define BB 512
#define SS 4096
#define DD 128
#define KK 409
#define VV 6
#define NT 256

// -------- global scratch (plain overwrites only; deterministic) --------
__device__ float g_sc [VV];
__device__ float g_U  [VV][64];     // U[v][n] = att_v . C1[:,n]

// ===========================================================================
// K1: 12 CTAs. blocks 0..5 -> score MLP per class; 6..11 -> attention+U.
// ===========================================================================
__global__ void __launch_bounds__(NT)
k1_tables(const float* __restrict__ emb,
          const float* __restrict__ W1, const float* __restrict__ b1,
          const float* __restrict__ W2, const float* __restrict__ b2,
          const float* __restrict__ W3, const float* __restrict__ b3,
          const float* __restrict__ A1, const float* __restrict__ a1,
          const float* __restrict__ A2, const float* __restrict__ a2,
          const float* __restrict__ C1) {
    const int tid = threadIdx.x;
    const int bid = blockIdx.x;
    __shared__ float e_s[DD];
    __shared__ float h1_s[64];
    __shared__ float h2_s[32];
    __shared__ float att_s[DD];

    const int v = (bid < VV) ? bid : bid - VV;
    if (tid < DD) e_s[tid] = emb[v * DD + tid];
    __syncthreads();

    if (bid < VV) {
        // ---- score chain: e -> h1(64) -> h2(32) -> score ----
        {   // 4 threads/neuron, 8-way ILP
            const int n = tid >> 2, q = tid & 3;
            const int i0 = q * 32;
            float acc[8] = {0, 0, 0, 0, 0, 0, 0, 0};
            #pragma unroll
            for (int m = 0; m < 4; m++)
                #pragma unroll
                for (int j = 0; j < 8; j++) {
                    const int i = i0 + m * 8 + j;
                    acc[j] = fmaf(e_s[i], W1[i * 64 + n], acc[j]);
                }
            float s = ((acc[0] + acc[1]) + (acc[2] + acc[3]))
                    + ((acc[4] + acc[5]) + (acc[6] + acc[7]));
            s += __shfl_down_sync(0xFFFFFFFFu, s, 2);
            s += __shfl_down_sync(0xFFFFFFFFu, s, 1);
            if (q == 0) h1_s[n] = fmaxf(s + b1[n], 0.f);
        }
        __syncthreads();
        {   // 8 threads/neuron
            const int n = tid >> 3, r = tid & 7;
            float acc[8];
            #pragma unroll
            for (int j = 0; j < 8; j++) {
                const int i = r + 8 * j;
                acc[j] = h1_s[i] * W2[i * 32 + n];
            }
            float s = ((acc[0] + acc[1]) + (acc[2] + acc[3]))
                    + ((acc[4] + acc[5]) + (acc[6] + acc[7]));
            s += __shfl_down_sync(0xFFFFFFFFu, s, 4);
            s += __shfl_down_sync(0xFFFFFFFFu, s, 2);
            s += __shfl_down_sync(0xFFFFFFFFu, s, 1);
            if (r == 0) h2_s[n] = fmaxf(s + b2[n], 0.f);
        }
        __syncthreads();
        if (tid < 32) {
            float s = h2_s[tid] * W3[tid];
            #pragma unroll
            for (int o = 16; o; o >>= 1) s += __shfl_down_sync(0xFFFFFFFFu, s, o);
            if (tid == 0) g_sc[v] = 1.f / (1.f + expf(-(s + b3[0])));
        }
    } else {
        // ---- attention chain: e -> g(64) -> att(128) -> U(64) ----
        {
            const int n = tid >> 2, q = tid & 3;
            const int i0 = q * 32;
            float acc[8] = {0, 0, 0, 0, 0, 0, 0, 0};
            #pragma unroll
            for (int m = 0; m < 4; m++)
                #pragma unroll
                for (int j = 0; j < 8; j++) {
                    const int i = i0 + m * 8 + j;
                    acc[j] = fmaf(e_s[i], A1[i * 64 + n], acc[j]);
                }
            float s = ((acc[0] + acc[1]) + (acc[2] + acc[3]))
                    + ((acc[4] + acc[5]) + (acc[6] + acc[7]));
            s += __shfl_down_sync(0xFFFFFFFFu, s, 2);
            s += __shfl_down_sync(0xFFFFFFFFu, s, 1);
            if (q == 0) h1_s[n] = fmaxf(s + a1[n], 0.f);   // g
        }
        __syncthreads();
        {   // att: 2 threads per output dim
            const int d = tid >> 1, q = tid & 1;
            const int j0 = q * 32;
            float acc[8] = {0, 0, 0, 0, 0, 0, 0, 0};
            #pragma unroll
            for (int m = 0; m < 4; m++)
                #pragma unroll
                for (int jj = 0; jj < 8; jj++) {
                    const int j = j0 + m * 8 + jj;
                    acc[jj] = fmaf(h1_s[j], A2[j * DD + d], acc[jj]);
                }
            float s = ((acc[0] + acc[1]) + (acc[2] + acc[3]))
                    + ((acc[4] + acc[5]) + (acc[6] + acc[7]));
            s += __shfl_down_sync(0xFFFFFFFFu, s, 1);
            if (q == 0) att_s[d] = s + a2[d];
        }
        __syncthreads();
        {   // U[v][n] = att . C1[:,n]
            const int n = tid >> 2, q = tid & 3;
            const int i0 = q * 32;
            float acc[8] = {0, 0, 0, 0, 0, 0, 0, 0};
            #pragma unroll
            for (int m = 0; m < 4; m++)
                #pragma unroll
                for (int j = 0; j < 8; j++) {
                    const int i = i0 + m * 8 + j;
                    acc[j] = fmaf(att_s[i], C1[i * 64 + n], acc[j]);
                }
            float s = ((acc[0] + acc[1]) + (acc[2] + acc[3]))
                    + ((acc[4] + acc[5]) + (acc[6] + acc[7]));
            s += __shfl_down_sync(0xFFFFFFFFu, s, 2);
            s += __shfl_down_sync(0xFFFFFFFFu, s, 1);
            if (q == 0) g_U[v][n] = s;
        }
    }
}

// ===========================================================================
// K2: one CTA per row. Warp w owns tokens [w*512,(w+1)*512) as 4 coalesced
// groups of 128. Packed-u64 scans give in-row position prefixes; ranks,
// fs writes, top-k scatter, analytic selcnt and the classifier all in-CTA.
// ===========================================================================
__global__ void __launch_bounds__(NT)
k2_row(const int* __restrict__ x,
       const float* __restrict__ c1, const float* __restrict__ C2,
       const float* __restrict__ c2, float* __restrict__ out) {
    const int row = blockIdx.x;
    const int tid = threadIdx.x;
    const int w = tid >> 5, lane = tid & 31;

    __shared__ float sc_s[8];
    __shared__ unsigned long long wtot_s[8];
    __shared__ float scf[VV];
    __shared__ int   selcnt_sm[VV];
    __shared__ float part[2];

    float* __restrict__ top_out = out + BB;
    float* __restrict__ fs_out  = out + BB + (size_t)BB * KK;

    if (tid < VV) sc_s[tid] = g_sc[tid];
    if (tid < VV) selcnt_sm[tid] = 0;

    // ---- 4 coalesced int4 loads: group g at w*512 + g*128 + lane*4 ----
    const int4* rowp = reinterpret_cast<const int4*>(x + (size_t)row * SS) + w * 128 + lane;
    const int4 t0 = rowp[0];
    const int4 t1 = rowp[32];
    const int4 t2 = rowp[64];
    const int4 t3 = rowp[96];

    // ---- packed counts (10 bits/class; warp max 512 fits) ----
    unsigned long long c0 = (1ULL << (10 * t0.x)) + (1ULL << (10 * t0.y))
                          + (1ULL << (10 * t0.z)) + (1ULL << (10 * t0.w));
    unsigned long long c1p = (1ULL << (10 * t1.x)) + (1ULL << (10 * t1.y))
                           + (1ULL << (10 * t1.z)) + (1ULL << (10 * t1.w));
    unsigned long long c2p = (1ULL << (10 * t2.x)) + (1ULL << (10 * t2.y))
                           + (1ULL << (10 * t2.z)) + (1ULL << (10 * t2.w));
    unsigned long long c3p = (1ULL << (10 * t3.x)) + (1ULL << (10 * t3.y))
                           + (1ULL << (10 * t3.z)) + (1ULL << (10 * t3.w));

    // ---- 4 interleaved inclusive warp scans ----
    unsigned long long i0 = c0, i1 = c1p, i2 = c2p, i3 = c3p;
    #pragma unroll
    for (int off = 1; off < 32; off <<= 1) {
        const unsigned long long n0 = __shfl_up_sync(0xFFFFFFFFu, i0, off);
        const unsigned long long n1 = __shfl_up_sync(0xFFFFFFFFu, i1, off);
        const unsigned long long n2 = __shfl_up_sync(0xFFFFFFFFu, i2, off);
        const unsigned long long n3 = __shfl_up_sync(0xFFFFFFFFu, i3, off);
        if (lane >= off) { i0 += n0; i1 += n1; i2 += n2; i3 += n3; }
    }
    const unsigned long long g0t = __shfl_sync(0xFFFFFFFFu, i0, 31);
    const unsigned long long g1t = __shfl_sync(0xFFFFFFFFu, i1, 31);
    const unsigned long long g2t = __shfl_sync(0xFFFFFFFFu, i2, 31);

    // exclusive position prefixes within this warp's 512-token span
    unsigned long long E0 = i0 - c0;
    unsigned long long E1 = (i1 - c1p) + g0t;
    unsigned long long E2 = (i2 - c2p) + g0t + g1t;
    unsigned long long E3 = (i3 - c3p) + g0t + g1t + g2t;

    if (lane == 31) wtot_s[w] = i0 + i1 + i2 + i3;   // warp total (packed)
    __syncthreads();

    // ---- lanes 0..5 (every warp): per-class total, warp-prefix, base, mask ----
    int tot = 0, wpre = 0, b = 0; unsigned m = 0;
    if (lane < VV) {
        #pragma unroll
        for (int i = 0; i < 8; i++) {
            const int e = (int)((wtot_s[i] >> (10 * lane)) & 1023ULL);
            tot += e;
            if (i < w) wpre += e;
        }
    }
    if (lane < VV) {
        const float sv = sc_s[lane];
        #pragma unroll
        for (int u = 0; u < VV; u++) {
            const int tu = __shfl_sync(0x3Fu, tot, u);
            const float su = sc_s[u];
            if (su > sv) b += tu;
            if (su == sv) m |= 1u << u;
        }
    }
    const bool tie =
        __ballot_sync(0xFFFFFFFFu, (lane < VV) && (m != (1u << lane))) != 0;
    const int B = b + wpre;   // fast-path combined base (valid lanes 0..5)

    // ---- final_scores writes (LUT, 4 coalesced float4 per thread) ----
    {
        float4* fo = reinterpret_cast<float4*>(fs_out + (size_t)row * SS) + w * 128 + lane;
        float4 f;
        f.x = sc_s[t0.x]; f.y = sc_s[t0.y]; f.z = sc_s[t0.z]; f.w = sc_s[t0.w]; fo[0]  = f;
        f.x = sc_s[t1.x]; f.y = sc_s[t1.y]; f.z = sc_s[t1.z]; f.w = sc_s[t1.w]; fo[32] = f;
        f.x = sc_s[t2.x]; f.y = sc_s[t2.y]; f.z = sc_s[t2.z]; f.w = sc_s[t2.w]; fo[64] = f;
        f.x = sc_s[t3.x]; f.y = sc_s[t3.y]; f.z = sc_s[t3.z]; f.w = sc_s[t3.w]; fo[96] = f;
    }

    const size_t obase = (size_t)row * KK;
    const int p0 = w * 512 + lane * 4;

    if (!tie) {
        // ---- fast path: rank = B_v + in-warp prefix, register-only ----
        #pragma unroll
        for (int g = 0; g < 4; g++) {
            const int4 t = (g == 0) ? t0 : (g == 1) ? t1 : (g == 2) ? t2 : t3;
            unsigned long long& E = (g == 0) ? E0 : (g == 1) ? E1 : (g == 2) ? E2 : E3;
            const int tk[4] = {t.x, t.y, t.z, t.w};
            #pragma unroll
            for (int j = 0; j < 4; j++) {
                const int v = tk[j];
                const int r = __shfl_sync(0xFFFFFFFFu, B, v)
                            + (int)((E >> (10 * v)) & 1023ULL);
                E += 1ULL << (10 * v);
                if (r < KK) top_out[obase + r] = (float)(p0 + g * 128 + j);
            }
        }
        // analytic selected counts (contiguous class ranges)
        if (w == 0 && lane < VV) {
            int sel = KK - b;
            sel = sel < 0 ? 0 : (sel > tot ? tot : sel);
            scf[lane] = (float)sel;
        }
    } else {
        // ---- tie path: exact lax.top_k mask semantics (in-CTA) ----
        int ls[VV] = {0, 0, 0, 0, 0, 0};
        #pragma unroll
        for (int g = 0; g < 4; g++) {
            const int4 t = (g == 0) ? t0 : (g == 1) ? t1 : (g == 2) ? t2 : t3;
            unsigned long long& E = (g == 0) ? E0 : (g == 1) ? E1 : (g == 2) ? E2 : E3;
            const int tk[4] = {t.x, t.y, t.z, t.w};
            #pragma unroll
            for (int j = 0; j < 4; j++) {
                const int v = tk[j];
                const unsigned mv = __shfl_sync(0xFFFFFFFFu, m, v);
                int r = __shfl_sync(0xFFFFFFFFu, b, v);
                #pragma unroll
                for (int u = 0; u < VV; u++)
                    if ((mv >> u) & 1u)
                        r += __shfl_sync(0xFFFFFFFFu, wpre, u)
                           + (int)((E >> (10 * u)) & 1023ULL);
                E += 1ULL << (10 * v);
                if (r < KK) {
                    top_out[obase + r] = (float)(p0 + g * 128 + j);
                    #pragma unroll
                    for (int u = 0; u < VV; u++) ls[u] += (v == u);
                }
            }
        }
        #pragma unroll
        for (int u = 0; u < VV; u++) {
            #pragma unroll
            for (int o = 16; o; o >>= 1) ls[u] += __shfl_down_sync(0xFFFFFFFFu, ls[u], o);
        }
        if (lane == 0) {
            #pragma unroll
            for (int u = 0; u < VV; u++)
                if (ls[u]) atomicAdd(&selcnt_sm[u], ls[u]);
        }
    }
    __syncthreads();
    if (tie && tid < VV) scf[tid] = (float)selcnt_sm[tid];
    if (tie) __syncthreads();

    // ---- classifier tail: h_n = relu(sum_v (cnt_v/K) U[v][n] + c1_n) ----
    if (tid < 64) {
        const float inv = 1.0f / (float)KK;
        float acc = c1[tid];
        #pragma unroll
        for (int v = 0; v < VV; v++)
            acc = fmaf(scf[v] * inv, g_U[v][tid], acc);
        float h = fmaxf(acc, 0.f) * C2[tid];
        #pragma unroll
        for (int o = 16; o; o >>= 1) h += __shfl_down_sync(0xFFFFFFFFu, h, o);
        if ((tid & 31) == 0) part[tid >> 5] = h;
    }
    __syncthreads();
    if (tid == 0)
        out[row] = 1.f / (1.f + expf(-(part[0] + part[1] + c2[0])));
}

// ===========================================================================
extern "C" void kernel_launch(void* const* d_in, const int* in_sizes, int n_in,
                              void* d_out, int out_size) {
    const int*   x   = (const int*)  d_in[0];
    const float* emb = (const float*)d_in[1];
    const float* W1  = (const float*)d_in[2];
    const float* b1  = (const float*)d_in[3];
    const float* W2  = (const float*)d_in[4];
    const float* b2  = (const float*)d_in[5];
    const float* W3  = (const float*)d_in[6];
    const float* b3  = (const float*)d_in[7];
    const float* A1  = (const float*)d_in[8];
    const float* a1  = (const float*)d_in[9];
    const float* A2  = (const float*)d_in[10];
    const float* a2  = (const float*)d_in[11];
    const float* C1  = (const float*)d_in[12];
    const float* c1  = (const float*)d_in[13];
    const float* C2  = (const float*)d_in[14];
    const float* c2  = (const float*)d_in[15];
    float* out = (float*)d_out;

    k1_tables<<<2 * VV, NT>>>(emb, W1, b1, W2, b2, W3, b3, A1, a1, A2, a2, C1);
    k2_row<<<BB, NT>>>(x, c1, C2, c2, out);
}